// round 16
// baseline (speedup 1.0000x reference)
#include <cuda_runtime.h>
#include <cstdint>

#define BV     32
#define TT     2048
#define DD     512
#define MAXRUN 1024
#define GBLK   912                  // 152 SMs * 6
#define RCAP   40                   // max runs staged per block (ceil(32768/912)=36)
#define CTf    0.7f
#define CPTf   0.5f

#define FMA2(acc, f, cc) asm("fma.rn.f32x2 %0, %1, %2, %0;" : "+l"(acc) : "l"(f), "l"(cc))
#define PACK2(d, c)      asm("mov.b64 %0, {%1, %1};" : "=l"(d) : "f"(c))
#define UNPK2(x, y, a)   asm("mov.b64 {%0, %1}, %2;" : "=f"(x), "=f"(y) : "l"(a))

// ---------------- device scratch (no allocations allowed) ----------------
__device__ float4   g_meta[BV * MAXRUN]; // {start, len, 1/cnt, 1/rep}, per-video compacted
__device__ unsigned g_mask[BV * MAXRUN]; // rep bitmask (first 32 rows of each qual run)
__device__ float    g_vid_attn[BV];
__device__ int      g_nqual[BV];
__device__ float    g_bsum[GBLK];
__device__ int      g_done;              // reset by last block each launch

// ============================================================================
// Kernel A: run analysis (unchanged from R14 — measured good).
// ============================================================================
__global__ __launch_bounds__(256) void runAnalysisKernel(const float* __restrict__ attn)
{
    __shared__ float         s_attn[TT];
    __shared__ unsigned char s_predB[258];
    __shared__ int           s_wTot[8];
    __shared__ int           s_total;
    __shared__ int           s_rstart[MAXRUN];
    __shared__ int           s_rend[MAXRUN];
    __shared__ int           s_wq[8];
    __shared__ float         s_red[8];

    const int b    = blockIdx.x;
    const int tid  = threadIdx.x;
    const int lane = tid & 31;
    const int warp = tid >> 5;
    const float* a_row = attn + (b << 11);

    const float4 v0 = ((const float4*)a_row)[tid * 2];
    const float4 v1 = ((const float4*)a_row)[tid * 2 + 1];
    ((float4*)s_attn)[tid * 2]     = v0;
    ((float4*)s_attn)[tid * 2 + 1] = v1;
    const float av[8] = {v0.x, v0.y, v0.z, v0.w, v1.x, v1.y, v1.z, v1.w};
    unsigned int pb = 0;
    #pragma unroll
    for (int j = 0; j < 8; j++) pb |= (av[j] > CPTf ? 1u : 0u) << j;
    s_predB[tid + 1] = (unsigned char)pb;
    if (tid == 0) { s_predB[0] = 0; s_predB[257] = 0; }
    __syncthreads();

    const unsigned prevB = s_predB[tid];
    const unsigned nextB = s_predB[tid + 2];
    const unsigned carry = (prevB >> 7) & 1u;
    const unsigned nxt   = (nextB & 1u) << 8;
    const unsigned ext   = pb | nxt;
    const unsigned stBits = pb & ~((pb << 1) | carry);
    const unsigned enBits = pb & ~(ext >> 1);

    int pref[8];
    int localTot = 0;
    #pragma unroll
    for (int j = 0; j < 8; j++) {
        localTot += (stBits >> j) & 1;
        pref[j] = localTot;
    }
    int incl = localTot;
    #pragma unroll
    for (int o = 1; o < 32; o <<= 1) {
        int u = __shfl_up_sync(0xffffffffu, incl, o);
        if (lane >= o) incl += u;
    }
    if (lane == 31) s_wTot[warp] = incl;
    __syncthreads();
    if (tid == 0) {
        int acc = 0;
        #pragma unroll
        for (int w = 0; w < 8; w++) { const int v = s_wTot[w]; s_wTot[w] = acc; acc += v; }
        s_total = acc;
    }
    __syncthreads();

    const int threadBase = s_wTot[warp] + (incl - localTot);
    const int base_t = tid * 8;
    #pragma unroll
    for (int j = 0; j < 8; j++) {
        const int rid = threadBase + pref[j] - 1;
        if ((stBits >> j) & 1) s_rstart[rid] = base_t + j;
        if ((enBits >> j) & 1) s_rend[rid]   = base_t + j;
    }
    __syncthreads();

    const int total = s_total;
    float attnAcc = 0.f;
    int      t0l[4], lenl[4];
    float    irl[4];
    unsigned mskl[4];
    int      q = 0;
    #pragma unroll
    for (int j = 0; j < 4; j++) {
        const int r = 4 * tid + j;
        t0l[j] = 0; lenl[j] = 0; irl[j] = 0.f; mskl[j] = 0u;
        if (r < total) {
            const int t0  = s_rstart[r];
            const int len = s_rend[r] - t0 + 1;
            float sum = 0.f; int rep = 0; unsigned mk = 0u;
            for (int l = 0; l < len; l++) {
                const float a = s_attn[t0 + l];
                sum += a;
                const int isrep = (a > CTf) ? 1 : 0;
                rep += isrep;
                if (l < 32) mk |= ((unsigned)isrep) << l;
            }
            const float mean = sum / (float)len;
            float ssq = 0.f;
            for (int l = 0; l < len; l++) {
                const float d = s_attn[t0 + l] - mean;
                ssq += d * d;
            }
            attnAcc += ssq / (float)len;
            t0l[j]  = t0;
            lenl[j] = len;
            irl[j]  = (rep > 0) ? (1.0f / (float)rep) : 0.0f;
            mskl[j] = mk;
            q += (rep > 0) ? 1 : 0;
        }
    }

    int qi = q;
    #pragma unroll
    for (int o = 1; o < 32; o <<= 1) {
        int u = __shfl_up_sync(0xffffffffu, qi, o);
        if (lane >= o) qi += u;
    }
    if (lane == 31) s_wq[warp] = qi;
    float ar = attnAcc;
    #pragma unroll
    for (int o = 16; o > 0; o >>= 1) ar += __shfl_xor_sync(0xffffffffu, ar, o);
    if (lane == 0) s_red[warp] = ar;
    __syncthreads();
    if (tid == 0) {
        int qa = 0; float asum = 0.f;
        #pragma unroll
        for (int w = 0; w < 8; w++) {
            const int tq = s_wq[w]; s_wq[w] = qa; qa += tq;
            asum += s_red[w];
        }
        g_vid_attn[b] = asum / (float)max(total, 1);
        g_nqual[b]    = qa;
    }
    __syncthreads();
    int slot = s_wq[warp] + (qi - q);
    #pragma unroll
    for (int j = 0; j < 4; j++) {
        if (irl[j] != 0.f) {
            float4 m;
            m.x = __int_as_float(t0l[j]);
            m.y = __int_as_float(lenl[j]);
            m.z = 1.0f / (float)lenl[j];
            m.w = irl[j];
            g_meta[(b << 10) + slot] = m;
            g_mask[(b << 10) + slot] = mskl[j];
            slot++;
        }
    }
}

// ============================================================================
// Kernel B: staged metadata; warp item = (run, half-D) = two adjacent quarters
// of the SAME run -> one meta/mask/trip-count, warp-uniform control, packed
// f32x2 FMAs on ulonglong2 loads. 6 blocks/SM for issue headroom.
// ============================================================================
__global__ __launch_bounds__(256, 6) void featKernel(const float* __restrict__ attn,
                                                     const float* __restrict__ feat,
                                                     float* __restrict__ out)
{
    __shared__ int      s_qbase[BV + 1];
    __shared__ float4   s_meta[RCAP];
    __shared__ unsigned s_mask[RCAP];
    __shared__ int      s_vid[RCAP];
    __shared__ float    s_part[8];
    __shared__ float    s_red[8];
    __shared__ int      s_isLast;

    const int tid  = threadIdx.x;
    const int lane = tid & 31;
    const int warp = tid >> 5;

    if (warp == 0) {                      // prefix of qual counts
        int nq = (lane < BV) ? g_nqual[lane] : 0;
        int sc = nq;
        #pragma unroll
        for (int o = 1; o < 32; o <<= 1) {
            int u = __shfl_up_sync(0xffffffffu, sc, o);
            if (lane >= o) sc += u;
        }
        if (lane < BV) s_qbase[lane + 1] = sc;
        if (lane == 0) s_qbase[0] = 0;
    }
    __syncthreads();
    const int Q      = s_qbase[BV];
    const int perBlk = (Q + (int)gridDim.x - 1) / (int)gridDim.x;
    const int r0     = blockIdx.x * perBlk;
    const int r1     = min(r0 + perBlk, Q);
    const int nr     = max(r1 - r0, 0);

    // ---- cooperative staging: one LDG round for all metas in range ----
    for (int i = tid; i < nr; i += 256) {
        const int g = r0 + i;
        int lo = 0, hi = BV;
        #pragma unroll
        for (int step = 0; step < 5; step++) {
            const int mid = (lo + hi) >> 1;
            if (s_qbase[mid] <= g) lo = mid; else hi = mid;
        }
        const int k = g - s_qbase[lo];
        s_meta[i] = __ldg(g_meta + (lo << 10) + k);
        s_mask[i] = __ldg(g_mask + (lo << 10) + k);
        s_vid[i]  = lo;
    }
    __syncthreads();

    // ---- items: (staged run, half-D). Warp-uniform inner loop. ----
    const int pairs = nr << 1;
    float ts = 0.f;

    for (int p = warp; p < pairs; p += 8) {
        const int i = p >> 1;
        const int h = p & 1;

        const float4   m = s_meta[i];
        const unsigned M = s_mask[i];
        const int      b = s_vid[i];

        const int   s    = __float_as_int(m.x);
        const int   L    = __float_as_int(m.y);
        const float cnon = m.z;
        const float crep = m.z - m.w;

        // two adjacent quarters: float4 index (h*64 + lane) and (+32)
        const ulonglong2* fb = (const ulonglong2*)feat
                             + ((size_t)((b << 11) + s)) * 128 + (h << 6) + lane;

        unsigned long long a0x = 0ull, a0y = 0ull, a1x = 0ull, a1y = 0ull;

        const int lim = min(L, 32);
        int j = 0;
        for (; j + 2 <= lim; j += 2) {
            const ulonglong2 f0a = __ldg(fb + (size_t)j * 128);
            const ulonglong2 f1a = __ldg(fb + (size_t)j * 128 + 32);
            const ulonglong2 f0b = __ldg(fb + (size_t)(j + 1) * 128);
            const ulonglong2 f1b = __ldg(fb + (size_t)(j + 1) * 128 + 32);
            const float c0 = ((M >> j) & 1u) ? crep : cnon;
            const float c1 = ((M >> (j + 1)) & 1u) ? crep : cnon;
            unsigned long long cc0, cc1;
            PACK2(cc0, c0);
            PACK2(cc1, c1);
            FMA2(a0x, f0a.x, cc0); FMA2(a0y, f0a.y, cc0);
            FMA2(a1x, f1a.x, cc0); FMA2(a1y, f1a.y, cc0);
            FMA2(a0x, f0b.x, cc1); FMA2(a0y, f0b.y, cc1);
            FMA2(a1x, f1b.x, cc1); FMA2(a1y, f1b.y, cc1);
        }
        if (j < lim) {
            const ulonglong2 f0 = __ldg(fb + (size_t)j * 128);
            const ulonglong2 f1 = __ldg(fb + (size_t)j * 128 + 32);
            const float c = ((M >> j) & 1u) ? crep : cnon;
            unsigned long long cc;
            PACK2(cc, c);
            FMA2(a0x, f0.x, cc); FMA2(a0y, f0.y, cc);
            FMA2(a1x, f1.x, cc); FMA2(a1y, f1.y, cc);
            j++;
        }
        if (L > 32) {                       // exactness tail (never hit for uniform data)
            const float* arow = attn + (b << 11) + s;
            for (; j < L; j++) {
                const float a = __ldg(arow + j);
                const ulonglong2 f0 = __ldg(fb + (size_t)j * 128);
                const ulonglong2 f1 = __ldg(fb + (size_t)j * 128 + 32);
                const float c = (a > CTf) ? crep : cnon;
                unsigned long long cc;
                PACK2(cc, c);
                FMA2(a0x, f0.x, cc); FMA2(a0y, f0.y, cc);
                FMA2(a1x, f1.x, cc); FMA2(a1y, f1.y, cc);
            }
        }

        float x0, y0, x1, y1, x2, y2, x3, y3;
        UNPK2(x0, y0, a0x); UNPK2(x1, y1, a0y);
        UNPK2(x2, y2, a1x); UNPK2(x3, y3, a1y);
        ts += x0*x0 + y0*y0 + x1*x1 + y1*y1
            + x2*x2 + y2*y2 + x3*x3 + y3*y3;
    }

    #pragma unroll
    for (int o = 16; o > 0; o >>= 1) ts += __shfl_xor_sync(0xffffffffu, ts, o);
    if (lane == 0) s_part[warp] = ts;
    __syncthreads();
    if (tid == 0) {
        float tot = 0.f;
        #pragma unroll
        for (int w = 0; w < 8; w++) tot += s_part[w];
        g_bsum[blockIdx.x] = tot;
        __threadfence();
        const int old = atomicAdd(&g_done, 1);
        s_isLast = (old == (int)gridDim.x - 1) ? 1 : 0;
    }
    __syncthreads();

    if (s_isLast) {
        __threadfence();
        float acc = 0.f;
        for (int i = tid; i < GBLK; i += 256) acc += g_bsum[i];
        #pragma unroll
        for (int o = 16; o > 0; o >>= 1) acc += __shfl_xor_sync(0xffffffffu, acc, o);
        if (lane == 0) s_red[warp] = acc;
        __syncthreads();
        if (tid == 0) {
            float f = 0.f;
            #pragma unroll
            for (int w = 0; w < 8; w++) f += s_red[w];
            float asum = 0.f; int qs = 0;
            #pragma unroll
            for (int v = 0; v < BV; v++) { asum += g_vid_attn[v]; qs += g_nqual[v]; }
            const float feat_loss = (f * (1.0f / (float)DD)) / (float)max(qs, 1);
            const float attn_loss = asum / (float)BV;
            out[0] = feat_loss + attn_loss;   // FW = AW = 1
            g_done = 0;                       // reset for next graph replay
        }
    }
}

// ============================================================================
extern "C" void kernel_launch(void* const* d_in, const int* in_sizes, int n_in,
                              void* d_out, int out_size)
{
    const float* attn = (const float*)d_in[0];
    const float* feat = (const float*)d_in[1];
    if (n_in >= 2 && in_sizes[0] > in_sizes[1]) {
        const float* tmp = attn; attn = feat; feat = tmp;
    }

    runAnalysisKernel<<<BV, 256>>>(attn);
    featKernel<<<GBLK, 256>>>(attn, feat, (float*)d_out);
}